// round 11
// baseline (speedup 1.0000x reference)
#include <cuda_runtime.h>

#define B_MAX 4096
#define GPB   16     // graphs per prep block
#define GPF   8      // graphs per final block

// Scratch (device globals — allocation is forbidden). 16B-aligned for float4.
__device__ __align__(16) float g_w[B_MAX * 128];     // per-graph gate vector  w_b = Wk @ q_b
__device__ __align__(16) float g_c[B_MAX];           // per-graph gate bias    c_b = bk . q_b
__device__ __align__(16) float g_xagg[B_MAX * 128];  // gated segment sums
__device__ __align__(16) float g_wkT[64 * 128];      // Wk transposed [h][f]

// ---------------------------------------------------------------------------
// Kernel 0: transpose Wk (128x64 -> 64x128).
// ---------------------------------------------------------------------------
__global__ void transpose_wk(const float* __restrict__ Wk) {
    int i = blockIdx.x * 256 + threadIdx.x;
    if (i < 128 * 64) {
        int f = i >> 6, h = i & 63;
        g_wkT[h * 128 + f] = Wk[i];
    }
}

// ---------------------------------------------------------------------------
// Kernel 1: per-graph precompute (R5 form).
//   q_b = u_b @ Wq + bq ; w_b = Wk @ q_b ; c_b = bk . q_b ; zero g_xagg.
// ---------------------------------------------------------------------------
__global__ void __launch_bounds__(256)
prep_kernel(const float* __restrict__ u,
            const float* __restrict__ bk,
            const float* __restrict__ Wq,
            const float* __restrict__ bq,
            int B) {
    __shared__ float su[GPB * 128];        // 8 KB
    __shared__ float sq[GPB * 64];         // 4 KB

    const int tid = threadIdx.x;
    const int g0  = blockIdx.x * GPB;

    for (int i = tid; i < GPB * 32; i += 256) {
        int g = i >> 5, c = i & 31;
        ((float4*)su)[i] = ((const float4*)(u + (size_t)(g0 + g) * 128))[c];
    }
    __syncthreads();

    // q phase: thread = (gq, h); gq owns graphs gq*4..gq*4+3
    {
        const int h = tid & 63, gq = tid >> 6;
        const float* s0 = su + (gq * 4 + 0) * 128;
        const float* s1 = su + (gq * 4 + 1) * 128;
        const float* s2 = su + (gq * 4 + 2) * 128;
        const float* s3 = su + (gq * 4 + 3) * 128;
        float a0 = bq[h], a1 = a0, a2 = a0, a3 = a0;
#pragma unroll 4
        for (int f = 0; f < 128; f++) {
            const float wq = Wq[f * 64 + h];   // coalesced across lanes (h)
            a0 += s0[f] * wq;                  // smem broadcast
            a1 += s1[f] * wq;
            a2 += s2[f] * wq;
            a3 += s3[f] * wq;
        }
        sq[(gq * 4 + 0) * 64 + h] = a0;
        sq[(gq * 4 + 1) * 64 + h] = a1;
        sq[(gq * 4 + 2) * 64 + h] = a2;
        sq[(gq * 4 + 3) * 64 + h] = a3;
    }
    __syncthreads();

    // c phase
    if (tid < GPB && g0 + tid < B) {
        float s = 0.0f;
        const float* qr = sq + tid * 64;
#pragma unroll 8
        for (int h = 0; h < 64; h++) s += bk[h] * qr[h];
        g_c[g0 + tid] = s;
    }

    // w phase: thread = (q8, f); q8 owns graphs q8*8..q8*8+7.
    {
        const int f = tid & 127, q8 = tid >> 7;
        float acc[8];
#pragma unroll
        for (int j = 0; j < 8; j++) acc[j] = 0.0f;
#pragma unroll 4
        for (int h = 0; h < 64; h++) {
            const float wk = g_wkT[h * 128 + f];   // coalesced, L2-resident
#pragma unroll
            for (int j = 0; j < 8; j++) acc[j] += sq[(q8 * 8 + j) * 64 + h] * wk;
        }
#pragma unroll
        for (int j = 0; j < 8; j++) {
            const int g = g0 + q8 * 8 + j;
            if (g < B) {
                g_w[(size_t)g * 128 + f]    = acc[j];
                g_xagg[(size_t)g * 128 + f] = 0.0f;
            }
        }
    }
}

// ---------------------------------------------------------------------------
// Kernel 2: HBM-bound streaming pass over x (512 MB). One warp per node,
// unrolled x8 (4 KB outstanding per warp); w-vector + bias cached in
// registers across the sorted segment.
// ---------------------------------------------------------------------------
__device__ __forceinline__ float warp_sum(float d) {
    d += __shfl_xor_sync(0xffffffffu, d, 16);
    d += __shfl_xor_sync(0xffffffffu, d, 8);
    d += __shfl_xor_sync(0xffffffffu, d, 4);
    d += __shfl_xor_sync(0xffffffffu, d, 2);
    d += __shfl_xor_sync(0xffffffffu, d, 1);
    return d;
}

__global__ void __launch_bounds__(256)
main_kernel(const float* __restrict__ x,
            const int* __restrict__ batch,
            int N, int chunk) {
    const int warp = threadIdx.x >> 5;
    const int lane = threadIdx.x & 31;
    long start = (long)blockIdx.x * chunk;
    long end   = start + chunk;
    if (end > N) end = N;

    float4 acc = make_float4(0.f, 0.f, 0.f, 0.f);
    float4 wv  = make_float4(0.f, 0.f, 0.f, 0.f);
    float  cb  = 0.0f;
    int    cur = -1;

    long node = start + warp;
    const long lim8 = end - 56;

#define PROC(bi, xi)                                                    \
        if (bi != cur) {                                                \
            if (cur >= 0) {                                             \
                float* p = g_xagg + (size_t)cur * 128 + lane * 4;       \
                atomicAdd(p + 0, acc.x); atomicAdd(p + 1, acc.y);       \
                atomicAdd(p + 2, acc.z); atomicAdd(p + 3, acc.w);       \
            }                                                           \
            acc = make_float4(0.f, 0.f, 0.f, 0.f);                      \
            cur = bi;                                                   \
            wv  = __ldg((const float4*)(g_w + (size_t)bi * 128) + lane);\
            cb  = g_c[bi];                                              \
        }                                                               \
        {                                                               \
            float d = xi.x * wv.x + xi.y * wv.y + xi.z * wv.z + xi.w * wv.w; \
            d = warp_sum(d);                                            \
            const float a = 1.0f / (1.0f + __expf(-(d + cb)));          \
            acc.x += a * xi.x; acc.y += a * xi.y;                       \
            acc.z += a * xi.z; acc.w += a * xi.w;                       \
        }

    for (; node < lim8; node += 64) {
        int    b[8];
        float4 xv[8];
#pragma unroll
        for (int t = 0; t < 8; t++) b[t] = batch[node + t * 8] & (B_MAX - 1);
#pragma unroll
        for (int t = 0; t < 8; t++)
            xv[t] = __ldcs((const float4*)(x + (size_t)(node + t * 8) * 128) + lane);
#pragma unroll
        for (int t = 0; t < 8; t++) {
            PROC(b[t], xv[t])
        }
    }

    for (; node < end; node += 8) {
        const int bb = batch[node] & (B_MAX - 1);
        const float4 xs = __ldcs((const float4*)(x + (size_t)node * 128) + lane);
        PROC(bb, xs)
    }
#undef PROC

    if (cur >= 0) {
        float* p = g_xagg + (size_t)cur * 128 + lane * 4;
        atomicAdd(p + 0, acc.x); atomicAdd(p + 1, acc.y);
        atomicAdd(p + 2, acc.z); atomicAdd(p + 3, acc.w);
    }
}

// ---------------------------------------------------------------------------
// Kernel 3: out = concat(x_agg, u) @ Wu + bu.  (R7 shape + minOccupancy=3)
// 512 threads = (quarter 0..3, j 0..127), split-K x4, GPF=8 -> 512 blocks.
// ---------------------------------------------------------------------------
__global__ void __launch_bounds__(512, 3)
final_kernel(const float* __restrict__ u,
             const float* __restrict__ Wu,
             const float* __restrict__ bu,
             float* __restrict__ out,
             int B) {
    __shared__ __align__(16) float s[GPF * 256];     // 8 KB concat inputs
    __shared__ float spart[3 * GPF * 128];           // 12 KB partials (quarters 1-3)
    const int j       = threadIdx.x & 127;  // output column
    const int quarter = threadIdx.x >> 7;   // 0..3, owns 64 K-values
    const int g0      = blockIdx.x * GPF;

    // stage concat(x_agg, u) rows, float4-vectorized
    for (int idx = threadIdx.x; idx < GPF * 64; idx += 512) {
        int g = idx >> 6, c = idx & 63;   // c: float4 index within 256-float row
        float4 v;
        if (g0 + g < B)
            v = (c < 32) ? ((const float4*)(g_xagg + (size_t)(g0 + g) * 128))[c]
                         : ((const float4*)(u      + (size_t)(g0 + g) * 128))[c - 32];
        else
            v = make_float4(0.f, 0.f, 0.f, 0.f);
        ((float4*)s)[g * 64 + c] = v;
    }
    __syncthreads();

    float acc[GPF];
#pragma unroll
    for (int g = 0; g < GPF; g++) acc[g] = 0.0f;

    const int i0 = quarter * 64;
#pragma unroll
    for (int ii = 0; ii < 64; ii += 8) {
        float wv[8];
#pragma unroll
        for (int t = 0; t < 8; t++)            // 8 independent coalesced LDGs
            wv[t] = Wu[(size_t)(i0 + ii + t) * 128 + j];
#pragma unroll
        for (int g = 0; g < GPF; g++) {
            const float4 sa = *(const float4*)&s[g * 256 + i0 + ii];
            const float4 sb = *(const float4*)&s[g * 256 + i0 + ii + 4];
            acc[g] += sa.x * wv[0] + sa.y * wv[1] + sa.z * wv[2] + sa.w * wv[3]
                    + sb.x * wv[4] + sb.y * wv[5] + sb.z * wv[6] + sb.w * wv[7];
        }
    }

    if (quarter != 0) {
#pragma unroll
        for (int g = 0; g < GPF; g++)
            spart[(quarter - 1) * GPF * 128 + g * 128 + j] = acc[g];
    }
    __syncthreads();
    if (quarter == 0) {
        const float b0 = bu[j];
#pragma unroll
        for (int g = 0; g < GPF; g++)
            if (g0 + g < B)
                out[(size_t)(g0 + g) * 128 + j] =
                    acc[g] + spart[0 * GPF * 128 + g * 128 + j]
                           + spart[1 * GPF * 128 + g * 128 + j]
                           + spart[2 * GPF * 128 + g * 128 + j] + b0;
    }
}

// ---------------------------------------------------------------------------
// Launch
// ---------------------------------------------------------------------------
extern "C" void kernel_launch(void* const* d_in, const int* in_sizes, int n_in,
                              void* d_out, int out_size) {
    const float* x     = (const float*)d_in[0];
    // d_in[1] = edge_index (unused), d_in[2] = e (unused)
    const float* u     = (const float*)d_in[3];
    const int*   batch = (const int*)d_in[4];   // int64 in reference -> int32 on device
    const float* Wk    = (const float*)d_in[5];
    const float* bk    = (const float*)d_in[6];
    const float* Wq    = (const float*)d_in[7];
    const float* bq    = (const float*)d_in[8];
    const float* Wu    = (const float*)d_in[9];
    const float* bu    = (const float*)d_in[10];
    float* out = (float*)d_out;

    const int N = in_sizes[0] / 128;   // 1,000,000
    const int B = out_size / 128;      // 4096

    transpose_wk<<<32, 256>>>(Wk);
    prep_kernel<<<(B + GPB - 1) / GPB, 256>>>(u, bk, Wq, bq, B);

    const int chunk = 1024;
    const int grid  = (N + chunk - 1) / chunk;
    main_kernel<<<grid, 256>>>(x, batch, N, chunk);

    final_kernel<<<(B + GPF - 1) / GPF, 512>>>(u, Wu, bu, out, B);
}

// round 12
// speedup vs baseline: 1.1245x; 1.1245x over previous
#include <cuda_runtime.h>

#define B_MAX 4096
#define GPB   16     // graphs per prep block
#define GPF   8      // graphs per final block

// Scratch (device globals — allocation is forbidden). 16B-aligned for float4.
__device__ __align__(16) float g_w[B_MAX * 128];     // per-graph gate vector  w_b = Wk @ q_b
__device__ __align__(16) float g_c[B_MAX];           // per-graph gate bias    c_b = bk . q_b
__device__ __align__(16) float g_xagg[B_MAX * 128];  // gated segment sums
__device__ __align__(16) float g_wkT[64 * 128];      // Wk transposed [h][f]

// ---------------------------------------------------------------------------
// Kernel 0: transpose Wk (128x64 -> 64x128).
// ---------------------------------------------------------------------------
__global__ void transpose_wk(const float* __restrict__ Wk) {
    int i = blockIdx.x * 256 + threadIdx.x;
    if (i < 128 * 64) {
        int f = i >> 6, h = i & 63;
        g_wkT[h * 128 + f] = Wk[i];
    }
}

// ---------------------------------------------------------------------------
// Kernel 1: per-graph precompute.
//   q_b = u_b @ Wq + bq ; w_b = Wk @ q_b ; c_b = bk . q_b ; zero g_xagg.
// ---------------------------------------------------------------------------
__global__ void __launch_bounds__(256)
prep_kernel(const float* __restrict__ u,
            const float* __restrict__ bk,
            const float* __restrict__ Wq,
            const float* __restrict__ bq,
            int B) {
    __shared__ float su[GPB * 128];        // 8 KB
    __shared__ float sq[GPB * 64];         // 4 KB

    const int tid = threadIdx.x;
    const int g0  = blockIdx.x * GPB;

    for (int i = tid; i < GPB * 32; i += 256) {
        int g = i >> 5, c = i & 31;
        ((float4*)su)[i] = ((const float4*)(u + (size_t)(g0 + g) * 128))[c];
    }
    __syncthreads();

    // q phase: thread = (gq, h); gq owns graphs gq*4..gq*4+3
    {
        const int h = tid & 63, gq = tid >> 6;
        const float* s0 = su + (gq * 4 + 0) * 128;
        const float* s1 = su + (gq * 4 + 1) * 128;
        const float* s2 = su + (gq * 4 + 2) * 128;
        const float* s3 = su + (gq * 4 + 3) * 128;
        float a0 = bq[h], a1 = a0, a2 = a0, a3 = a0;
#pragma unroll 4
        for (int f = 0; f < 128; f++) {
            const float wq = Wq[f * 64 + h];   // coalesced across lanes (h)
            a0 += s0[f] * wq;                  // smem broadcast
            a1 += s1[f] * wq;
            a2 += s2[f] * wq;
            a3 += s3[f] * wq;
        }
        sq[(gq * 4 + 0) * 64 + h] = a0;
        sq[(gq * 4 + 1) * 64 + h] = a1;
        sq[(gq * 4 + 2) * 64 + h] = a2;
        sq[(gq * 4 + 3) * 64 + h] = a3;
    }
    __syncthreads();

    // c phase
    if (tid < GPB && g0 + tid < B) {
        float s = 0.0f;
        const float* qr = sq + tid * 64;
#pragma unroll 8
        for (int h = 0; h < 64; h++) s += bk[h] * qr[h];
        g_c[g0 + tid] = s;
    }

    // w phase: thread = (q8, f); q8 owns graphs q8*8..q8*8+7.
    {
        const int f = tid & 127, q8 = tid >> 7;
        float acc[8];
#pragma unroll
        for (int j = 0; j < 8; j++) acc[j] = 0.0f;
#pragma unroll 4
        for (int h = 0; h < 64; h++) {
            const float wk = g_wkT[h * 128 + f];   // coalesced, L2-resident
#pragma unroll
            for (int j = 0; j < 8; j++) acc[j] += sq[(q8 * 8 + j) * 64 + h] * wk;
        }
#pragma unroll
        for (int j = 0; j < 8; j++) {
            const int g = g0 + q8 * 8 + j;
            if (g < B) {
                g_w[(size_t)g * 128 + f]    = acc[j];
                g_xagg[(size_t)g * 128 + f] = 0.0f;
            }
        }
    }
}

// ---------------------------------------------------------------------------
// Kernel 2: HBM-bound streaming pass over x (512 MB). One warp per node,
// unrolled x4 (best measured; x8 regressed via register pressure); w-vector
// + bias cached in registers across the sorted segment.
// ---------------------------------------------------------------------------
__device__ __forceinline__ float warp_sum(float d) {
    d += __shfl_xor_sync(0xffffffffu, d, 16);
    d += __shfl_xor_sync(0xffffffffu, d, 8);
    d += __shfl_xor_sync(0xffffffffu, d, 4);
    d += __shfl_xor_sync(0xffffffffu, d, 2);
    d += __shfl_xor_sync(0xffffffffu, d, 1);
    return d;
}

__global__ void __launch_bounds__(256)
main_kernel(const float* __restrict__ x,
            const int* __restrict__ batch,
            int N, int chunk) {
    const int warp = threadIdx.x >> 5;
    const int lane = threadIdx.x & 31;
    long start = (long)blockIdx.x * chunk;
    long end   = start + chunk;
    if (end > N) end = N;

    float4 acc = make_float4(0.f, 0.f, 0.f, 0.f);
    float4 wv  = make_float4(0.f, 0.f, 0.f, 0.f);
    float  cb  = 0.0f;
    int    cur = -1;

    long node = start + warp;
    const long lim4 = end - 24;

#define PROC(bi, xi)                                                    \
        if (bi != cur) {                                                \
            if (cur >= 0) {                                             \
                float* p = g_xagg + (size_t)cur * 128 + lane * 4;       \
                atomicAdd(p + 0, acc.x); atomicAdd(p + 1, acc.y);       \
                atomicAdd(p + 2, acc.z); atomicAdd(p + 3, acc.w);       \
            }                                                           \
            acc = make_float4(0.f, 0.f, 0.f, 0.f);                      \
            cur = bi;                                                   \
            wv  = __ldg((const float4*)(g_w + (size_t)bi * 128) + lane);\
            cb  = g_c[bi];                                              \
        }                                                               \
        {                                                               \
            float d = xi.x * wv.x + xi.y * wv.y + xi.z * wv.z + xi.w * wv.w; \
            d = warp_sum(d);                                            \
            const float a = 1.0f / (1.0f + __expf(-(d + cb)));          \
            acc.x += a * xi.x; acc.y += a * xi.y;                       \
            acc.z += a * xi.z; acc.w += a * xi.w;                       \
        }

    for (; node < lim4; node += 32) {
        const int b0 = batch[node]      & (B_MAX - 1);
        const int b1 = batch[node + 8]  & (B_MAX - 1);
        const int b2 = batch[node + 16] & (B_MAX - 1);
        const int b3 = batch[node + 24] & (B_MAX - 1);

        const float4 x0 = __ldcs((const float4*)(x + (size_t)(node)      * 128) + lane);
        const float4 x1 = __ldcs((const float4*)(x + (size_t)(node + 8)  * 128) + lane);
        const float4 x2 = __ldcs((const float4*)(x + (size_t)(node + 16) * 128) + lane);
        const float4 x3 = __ldcs((const float4*)(x + (size_t)(node + 24) * 128) + lane);

        PROC(b0, x0)
        PROC(b1, x1)
        PROC(b2, x2)
        PROC(b3, x3)
    }

    for (; node < end; node += 8) {
        const int b = batch[node] & (B_MAX - 1);
        const float4 xv = __ldcs((const float4*)(x + (size_t)node * 128) + lane);
        PROC(b, xv)
    }
#undef PROC

    if (cur >= 0) {
        float* p = g_xagg + (size_t)cur * 128 + lane * 4;
        atomicAdd(p + 0, acc.x); atomicAdd(p + 1, acc.y);
        atomicAdd(p + 2, acc.z); atomicAdd(p + 3, acc.w);
    }
}

// ---------------------------------------------------------------------------
// Kernel 3: out = concat(x_agg, u) @ Wu + bu.  (R7 shape — best measured:
// regs=48, no min-occupancy clause; issue/ILP-bound, occupancy not binding)
// 512 threads = (quarter 0..3, j 0..127), split-K x4, GPF=8 -> 512 blocks.
// ---------------------------------------------------------------------------
__global__ void __launch_bounds__(512)
final_kernel(const float* __restrict__ u,
             const float* __restrict__ Wu,
             const float* __restrict__ bu,
             float* __restrict__ out,
             int B) {
    __shared__ __align__(16) float s[GPF * 256];     // 8 KB concat inputs
    __shared__ float spart[3 * GPF * 128];           // 12 KB partials (quarters 1-3)
    const int j       = threadIdx.x & 127;  // output column
    const int quarter = threadIdx.x >> 7;   // 0..3, owns 64 K-values
    const int g0      = blockIdx.x * GPF;

    // stage concat(x_agg, u) rows, float4-vectorized
    for (int idx = threadIdx.x; idx < GPF * 64; idx += 512) {
        int g = idx >> 6, c = idx & 63;   // c: float4 index within 256-float row
        float4 v;
        if (g0 + g < B)
            v = (c < 32) ? ((const float4*)(g_xagg + (size_t)(g0 + g) * 128))[c]
                         : ((const float4*)(u      + (size_t)(g0 + g) * 128))[c - 32];
        else
            v = make_float4(0.f, 0.f, 0.f, 0.f);
        ((float4*)s)[g * 64 + c] = v;
    }
    __syncthreads();

    float acc[GPF];
#pragma unroll
    for (int g = 0; g < GPF; g++) acc[g] = 0.0f;

    const int i0 = quarter * 64;
#pragma unroll
    for (int ii = 0; ii < 64; ii += 8) {
        float wv[8];
#pragma unroll
        for (int t = 0; t < 8; t++)            // 8 independent coalesced LDGs
            wv[t] = Wu[(size_t)(i0 + ii + t) * 128 + j];
#pragma unroll
        for (int g = 0; g < GPF; g++) {
            const float4 sa = *(const float4*)&s[g * 256 + i0 + ii];
            const float4 sb = *(const float4*)&s[g * 256 + i0 + ii + 4];
            acc[g] += sa.x * wv[0] + sa.y * wv[1] + sa.z * wv[2] + sa.w * wv[3]
                    + sb.x * wv[4] + sb.y * wv[5] + sb.z * wv[6] + sb.w * wv[7];
        }
    }

    if (quarter != 0) {
#pragma unroll
        for (int g = 0; g < GPF; g++)
            spart[(quarter - 1) * GPF * 128 + g * 128 + j] = acc[g];
    }
    __syncthreads();
    if (quarter == 0) {
        const float b0 = bu[j];
#pragma unroll
        for (int g = 0; g < GPF; g++)
            if (g0 + g < B)
                out[(size_t)(g0 + g) * 128 + j] =
                    acc[g] + spart[0 * GPF * 128 + g * 128 + j]
                           + spart[1 * GPF * 128 + g * 128 + j]
                           + spart[2 * GPF * 128 + g * 128 + j] + b0;
    }
}

// ---------------------------------------------------------------------------
// Launch
// ---------------------------------------------------------------------------
extern "C" void kernel_launch(void* const* d_in, const int* in_sizes, int n_in,
                              void* d_out, int out_size) {
    const float* x     = (const float*)d_in[0];
    // d_in[1] = edge_index (unused), d_in[2] = e (unused)
    const float* u     = (const float*)d_in[3];
    const int*   batch = (const int*)d_in[4];   // int64 in reference -> int32 on device
    const float* Wk    = (const float*)d_in[5];
    const float* bk    = (const float*)d_in[6];
    const float* Wq    = (const float*)d_in[7];
    const float* bq    = (const float*)d_in[8];
    const float* Wu    = (const float*)d_in[9];
    const float* bu    = (const float*)d_in[10];
    float* out = (float*)d_out;

    const int N = in_sizes[0] / 128;   // 1,000,000
    const int B = out_size / 128;      // 4096

    transpose_wk<<<32, 256>>>(Wk);
    prep_kernel<<<(B + GPB - 1) / GPB, 256>>>(u, bk, Wq, bq, B);

    const int chunk = 1024;
    const int grid  = (N + chunk - 1) / chunk;
    main_kernel<<<grid, 256>>>(x, batch, N, chunk);

    final_kernel<<<(B + GPF - 1) / GPF, 512>>>(u, Wu, bu, out, B);
}

// round 13
// speedup vs baseline: 1.2191x; 1.0841x over previous
#include <cuda_runtime.h>

#define B_MAX 4096
#define GPB   16     // graphs per prep block
#define GPF   8      // graphs per final block
#define NSM   148    // GB300 SMs (152 on GB300 board; 148 conservative/even)

// Scratch (device globals — allocation is forbidden). 16B-aligned for float4.
__device__ __align__(16) float g_w[B_MAX * 128];     // per-graph gate vector  w_b = Wk @ q_b
__device__ __align__(16) float g_c[B_MAX];           // per-graph gate bias    c_b = bk . q_b
__device__ __align__(16) float g_xagg[B_MAX * 128];  // gated segment sums
__device__ __align__(16) float g_wkT[64 * 128];      // Wk transposed [h][f]

// ---------------------------------------------------------------------------
// Kernel 0: transpose Wk (128x64 -> 64x128).
// ---------------------------------------------------------------------------
__global__ void transpose_wk(const float* __restrict__ Wk) {
    int i = blockIdx.x * 256 + threadIdx.x;
    if (i < 128 * 64) {
        int f = i >> 6, h = i & 63;
        g_wkT[h * 128 + f] = Wk[i];
    }
}

// ---------------------------------------------------------------------------
// Kernel 1: per-graph precompute.
//   q_b = u_b @ Wq + bq ; w_b = Wk @ q_b ; c_b = bk . q_b ; zero g_xagg.
// ---------------------------------------------------------------------------
__global__ void __launch_bounds__(256)
prep_kernel(const float* __restrict__ u,
            const float* __restrict__ bk,
            const float* __restrict__ Wq,
            const float* __restrict__ bq,
            int B) {
    __shared__ float su[GPB * 128];        // 8 KB
    __shared__ float sq[GPB * 64];         // 4 KB

    const int tid = threadIdx.x;
    const int g0  = blockIdx.x * GPB;

    for (int i = tid; i < GPB * 32; i += 256) {
        int g = i >> 5, c = i & 31;
        ((float4*)su)[i] = ((const float4*)(u + (size_t)(g0 + g) * 128))[c];
    }
    __syncthreads();

    // q phase: thread = (gq, h); gq owns graphs gq*4..gq*4+3
    {
        const int h = tid & 63, gq = tid >> 6;
        const float* s0 = su + (gq * 4 + 0) * 128;
        const float* s1 = su + (gq * 4 + 1) * 128;
        const float* s2 = su + (gq * 4 + 2) * 128;
        const float* s3 = su + (gq * 4 + 3) * 128;
        float a0 = bq[h], a1 = a0, a2 = a0, a3 = a0;
#pragma unroll 4
        for (int f = 0; f < 128; f++) {
            const float wq = Wq[f * 64 + h];   // coalesced across lanes (h)
            a0 += s0[f] * wq;                  // smem broadcast
            a1 += s1[f] * wq;
            a2 += s2[f] * wq;
            a3 += s3[f] * wq;
        }
        sq[(gq * 4 + 0) * 64 + h] = a0;
        sq[(gq * 4 + 1) * 64 + h] = a1;
        sq[(gq * 4 + 2) * 64 + h] = a2;
        sq[(gq * 4 + 3) * 64 + h] = a3;
    }
    __syncthreads();

    // c phase
    if (tid < GPB && g0 + tid < B) {
        float s = 0.0f;
        const float* qr = sq + tid * 64;
#pragma unroll 8
        for (int h = 0; h < 64; h++) s += bk[h] * qr[h];
        g_c[g0 + tid] = s;
    }

    // w phase: thread = (q8, f); q8 owns graphs q8*8..q8*8+7.
    {
        const int f = tid & 127, q8 = tid >> 7;
        float acc[8];
#pragma unroll
        for (int j = 0; j < 8; j++) acc[j] = 0.0f;
#pragma unroll 4
        for (int h = 0; h < 64; h++) {
            const float wk = g_wkT[h * 128 + f];   // coalesced, L2-resident
#pragma unroll
            for (int j = 0; j < 8; j++) acc[j] += sq[(q8 * 8 + j) * 64 + h] * wk;
        }
#pragma unroll
        for (int j = 0; j < 8; j++) {
            const int g = g0 + q8 * 8 + j;
            if (g < B) {
                g_w[(size_t)g * 128 + f]    = acc[j];
                g_xagg[(size_t)g * 128 + f] = 0.0f;
            }
        }
    }
}

// ---------------------------------------------------------------------------
// Kernel 2: HBM-bound streaming pass over x (512 MB). One warp per node,
// unrolled x4; w-vector + bias cached in registers across the sorted segment.
// Grid = 148*8 blocks, equal chunks -> every SM hosts exactly 8 blocks with
// identical work (kills the 7-vs-6 blocks/SM imbalance of the 977-block grid).
// ---------------------------------------------------------------------------
__device__ __forceinline__ float warp_sum(float d) {
    d += __shfl_xor_sync(0xffffffffu, d, 16);
    d += __shfl_xor_sync(0xffffffffu, d, 8);
    d += __shfl_xor_sync(0xffffffffu, d, 4);
    d += __shfl_xor_sync(0xffffffffu, d, 2);
    d += __shfl_xor_sync(0xffffffffu, d, 1);
    return d;
}

__global__ void __launch_bounds__(256)
main_kernel(const float* __restrict__ x,
            const int* __restrict__ batch,
            int N, int chunk) {
    const int warp = threadIdx.x >> 5;
    const int lane = threadIdx.x & 31;
    long start = (long)blockIdx.x * chunk;
    long end   = start + chunk;
    if (end > N) end = N;

    float4 acc = make_float4(0.f, 0.f, 0.f, 0.f);
    float4 wv  = make_float4(0.f, 0.f, 0.f, 0.f);
    float  cb  = 0.0f;
    int    cur = -1;

    long node = start + warp;
    const long lim4 = end - 24;

#define PROC(bi, xi)                                                    \
        if (bi != cur) {                                                \
            if (cur >= 0) {                                             \
                float* p = g_xagg + (size_t)cur * 128 + lane * 4;       \
                atomicAdd(p + 0, acc.x); atomicAdd(p + 1, acc.y);       \
                atomicAdd(p + 2, acc.z); atomicAdd(p + 3, acc.w);       \
            }                                                           \
            acc = make_float4(0.f, 0.f, 0.f, 0.f);                      \
            cur = bi;                                                   \
            wv  = __ldg((const float4*)(g_w + (size_t)bi * 128) + lane);\
            cb  = g_c[bi];                                              \
        }                                                               \
        {                                                               \
            float d = xi.x * wv.x + xi.y * wv.y + xi.z * wv.z + xi.w * wv.w; \
            d = warp_sum(d);                                            \
            const float a = 1.0f / (1.0f + __expf(-(d + cb)));          \
            acc.x += a * xi.x; acc.y += a * xi.y;                       \
            acc.z += a * xi.z; acc.w += a * xi.w;                       \
        }

    for (; node < lim4; node += 32) {
        const int b0 = batch[node]      & (B_MAX - 1);
        const int b1 = batch[node + 8]  & (B_MAX - 1);
        const int b2 = batch[node + 16] & (B_MAX - 1);
        const int b3 = batch[node + 24] & (B_MAX - 1);

        const float4 x0 = __ldcs((const float4*)(x + (size_t)(node)      * 128) + lane);
        const float4 x1 = __ldcs((const float4*)(x + (size_t)(node + 8)  * 128) + lane);
        const float4 x2 = __ldcs((const float4*)(x + (size_t)(node + 16) * 128) + lane);
        const float4 x3 = __ldcs((const float4*)(x + (size_t)(node + 24) * 128) + lane);

        PROC(b0, x0)
        PROC(b1, x1)
        PROC(b2, x2)
        PROC(b3, x3)
    }

    for (; node < end; node += 8) {
        const int b = batch[node] & (B_MAX - 1);
        const float4 xv = __ldcs((const float4*)(x + (size_t)node * 128) + lane);
        PROC(b, xv)
    }
#undef PROC

    if (cur >= 0) {
        float* p = g_xagg + (size_t)cur * 128 + lane * 4;
        atomicAdd(p + 0, acc.x); atomicAdd(p + 1, acc.y);
        atomicAdd(p + 2, acc.z); atomicAdd(p + 3, acc.w);
    }
}

// ---------------------------------------------------------------------------
// Kernel 3: out = concat(x_agg, u) @ Wu + bu.  (best-measured R7 shape)
// 512 threads = (quarter 0..3, j 0..127), split-K x4, GPF=8 -> 512 blocks.
// ---------------------------------------------------------------------------
__global__ void __launch_bounds__(512)
final_kernel(const float* __restrict__ u,
             const float* __restrict__ Wu,
             const float* __restrict__ bu,
             float* __restrict__ out,
             int B) {
    __shared__ __align__(16) float s[GPF * 256];     // 8 KB concat inputs
    __shared__ float spart[3 * GPF * 128];           // 12 KB partials (quarters 1-3)
    const int j       = threadIdx.x & 127;  // output column
    const int quarter = threadIdx.x >> 7;   // 0..3, owns 64 K-values
    const int g0      = blockIdx.x * GPF;

    // stage concat(x_agg, u) rows, float4-vectorized
    for (int idx = threadIdx.x; idx < GPF * 64; idx += 512) {
        int g = idx >> 6, c = idx & 63;   // c: float4 index within 256-float row
        float4 v;
        if (g0 + g < B)
            v = (c < 32) ? ((const float4*)(g_xagg + (size_t)(g0 + g) * 128))[c]
                         : ((const float4*)(u      + (size_t)(g0 + g) * 128))[c - 32];
        else
            v = make_float4(0.f, 0.f, 0.f, 0.f);
        ((float4*)s)[g * 64 + c] = v;
    }
    __syncthreads();

    float acc[GPF];
#pragma unroll
    for (int g = 0; g < GPF; g++) acc[g] = 0.0f;

    const int i0 = quarter * 64;
#pragma unroll
    for (int ii = 0; ii < 64; ii += 8) {
        float wv[8];
#pragma unroll
        for (int t = 0; t < 8; t++)            // 8 independent coalesced LDGs
            wv[t] = Wu[(size_t)(i0 + ii + t) * 128 + j];
#pragma unroll
        for (int g = 0; g < GPF; g++) {
            const float4 sa = *(const float4*)&s[g * 256 + i0 + ii];
            const float4 sb = *(const float4*)&s[g * 256 + i0 + ii + 4];
            acc[g] += sa.x * wv[0] + sa.y * wv[1] + sa.z * wv[2] + sa.w * wv[3]
                    + sb.x * wv[4] + sb.y * wv[5] + sb.z * wv[6] + sb.w * wv[7];
        }
    }

    if (quarter != 0) {
#pragma unroll
        for (int g = 0; g < GPF; g++)
            spart[(quarter - 1) * GPF * 128 + g * 128 + j] = acc[g];
    }
    __syncthreads();
    if (quarter == 0) {
        const float b0 = bu[j];
#pragma unroll
        for (int g = 0; g < GPF; g++)
            if (g0 + g < B)
                out[(size_t)(g0 + g) * 128 + j] =
                    acc[g] + spart[0 * GPF * 128 + g * 128 + j]
                           + spart[1 * GPF * 128 + g * 128 + j]
                           + spart[2 * GPF * 128 + g * 128 + j] + b0;
    }
}

// ---------------------------------------------------------------------------
// Launch
// ---------------------------------------------------------------------------
extern "C" void kernel_launch(void* const* d_in, const int* in_sizes, int n_in,
                              void* d_out, int out_size) {
    const float* x     = (const float*)d_in[0];
    // d_in[1] = edge_index (unused), d_in[2] = e (unused)
    const float* u     = (const float*)d_in[3];
    const int*   batch = (const int*)d_in[4];   // int64 in reference -> int32 on device
    const float* Wk    = (const float*)d_in[5];
    const float* bk    = (const float*)d_in[6];
    const float* Wq    = (const float*)d_in[7];
    const float* bq    = (const float*)d_in[8];
    const float* Wu    = (const float*)d_in[9];
    const float* bu    = (const float*)d_in[10];
    float* out = (float*)d_out;

    const int N = in_sizes[0] / 128;   // 1,000,000
    const int B = out_size / 128;      // 4096

    transpose_wk<<<32, 256>>>(Wk);
    prep_kernel<<<(B + GPB - 1) / GPB, 256>>>(u, bk, Wq, bq, B);

    // Equal-work grid: exactly 8 blocks per SM, no 7-vs-6 imbalance.
    const int grid  = NSM * 8;                 // 1184
    const int chunk = (N + grid - 1) / grid;   // 845
    main_kernel<<<grid, 256>>>(x, batch, N, chunk);

    final_kernel<<<(B + GPF - 1) / GPF, 512>>>(u, Wu, bu, out, B);
}